// round 11
// baseline (speedup 1.0000x reference)
#include <cuda_runtime.h>
#include <cuda_fp16.h>

#define NN 100000
#define EE 1600000
#define DD 64
#define SCAN_T 1024
#define SCAN_B 98                 // ceil(NN/1024)
#define EDGE_BLOCKS 6250          // EE/256 exact
#define SN_BLOCKS 391             // ceil(NN/256)
#define MID_B 148
#define MID_T 1024
#define MID_STRIDE (MID_B * MID_T)
#define NGROUPS (NN / 4)          // 25000: 4 nodes per warp

// ---------------- scratch (static device globals; zero-init at load) --------
// Invariants at kernel_launch entry: g_deg, g_scanstate, g_smaxkey, g_bar1,
// g_bar2 are ZERO. True at load; g_deg/g_scanstate/g_smaxkey restored by
// k_mid phase B, bar counters by k_out.
__device__ unsigned g_smaxkey;
__device__ float    g_snode[NN];             // score, then exp(s-gmax) in-place
__device__ float    g_has[NN];
__device__ int      g_deg[NN];
__device__ int      g_off[NN + 1];
__device__ int      g_cur[NN];
__device__ int2     g_rc[EE];                // interleaved (row, col)
__device__ int      g_eidx[EE];              // CSR-by-dest: srcRow only
__device__ __half2  g_xh[(size_t)NN * 32];   // fp16 mirror of x
__device__ float    g_agg[(size_t)NN * DD];
__device__ unsigned long long g_scanstate[SCAN_B];  // (flag<<32)|value
__device__ int      g_bar1, g_bar2;          // device barrier counters

// ---------------- packed f32x2 FMA (2x fp32 FMA rate on sm_103a) ------------
union F2U { float2 f2; unsigned long long u; };
__device__ __forceinline__ F2U ffma2(F2U a, F2U b, F2U c) {
    F2U d;
    asm("fma.rn.f32x2 %0, %1, %2, %3;" : "=l"(d.u) : "l"(a.u), "l"(b.u), "l"(c.u));
    return d;
}

// ---------------- device-wide barrier (all MID_B blocks co-resident) --------
__device__ __forceinline__ void devbar(int* ctr) {
    __syncthreads();
    if (threadIdx.x == 0) {
        __threadfence();
        atomicAdd(ctr, 1);
        while (atomicAdd(ctr, 0) < MID_B) { }
    }
    __syncthreads();
}

// ---------------- K1: FUSED (edge convert + hist) || (scores + fp16 copy) ---
__global__ void __launch_bounds__(256) k_fused(
    const float* __restrict__ x, const void* __restrict__ ei,
    const float* __restrict__ Wm, const float* __restrict__ bm) {
    int b = blockIdx.x;
    int t = threadIdx.x;
    if (b < EDGE_BLOCKS) {
        // int64 detection: leading odd 32-bit words all zero <=> int64 ids.
        int2 probe = __ldg(&((const int2*)ei)[t]);
        int any = __syncthreads_or(probe.y);
        int e = b * 256 + t;
        int row, col;
        if (any == 0) {  // int64
            row = (int)__ldg(&((const long long*)ei)[e]);
            col = (int)__ldg(&((const long long*)ei)[(long long)EE + e]);
        } else {         // int32
            row = __ldg(&((const int*)ei)[e]);
            col = __ldg(&((const int*)ei)[EE + e]);
        }
        g_rc[e] = make_int2(row, col);
        atomicAdd(&g_deg[col], 1);
    } else {
        // ---- per-node score s = x[n].wbar + bmean ----
        __shared__ float swb[DD];
        __shared__ float sbm;
        if (t < DD) {
            float s = 0.f;
#pragma unroll
            for (int j = 0; j < DD; j++) s += __ldg(&Wm[t * DD + j]);
            swb[t] = s * (1.0f / DD);
        }
        if (t == 0) {
            float bs = 0.f;
            for (int j = 0; j < DD; j++) bs += __ldg(&bm[j]);
            sbm = bs * (1.0f / DD);
        }
        __syncthreads();
        int n0 = (b - EDGE_BLOCKS) * 256;
        int n = n0 + t;
        float s = -1e30f;
        if (n < NN) {
            const float4* xp = (const float4*)(x + (size_t)n * DD);
            float acc = 0.f;
#pragma unroll
            for (int i = 0; i < DD / 4; i++) {
                float4 v = __ldg(&xp[i]);
                acc += v.x * swb[4 * i] + v.y * swb[4 * i + 1] +
                       v.z * swb[4 * i + 2] + v.w * swb[4 * i + 3];
            }
            s = acc + sbm;  // BETA = 1.0
            g_snode[n] = s;
        }
        float m = s;
#pragma unroll
        for (int o = 16; o; o >>= 1) m = fmaxf(m, __shfl_xor_sync(0xffffffffu, m, o));
        if ((t & 31) == 0) {
            unsigned bb = __float_as_uint(m);
            unsigned key = (bb & 0x80000000u) ? ~bb : (bb | 0x80000000u);
            atomicMax(&g_smaxkey, key);
        }
        // ---- fp16 mirror, coalesced ----
        int lim = (NN - n0 < 256) ? (NN - n0) : 256;
        for (int j = t; j < lim * 32; j += 256) {
            int node = n0 + (j >> 5);
            int h = j & 31;
            float2 v = __ldg((const float2*)(x + (size_t)node * DD + 2 * h));
            g_xh[(size_t)node * 32 + h] = __floats2half2_rn(v.x, v.y);
        }
    }
}

// ---------------- K2: persistent scan -> scatter -> aggregate ---------------
// 148 blocks x 1024 threads, all co-resident; two device-wide barriers.
__global__ void __launch_bounds__(MID_T, 1) k_mid() {
    int b = blockIdx.x, t = threadIdx.x;

    // ======== Phase A: decoupled-lookback scan (blocks 0..SCAN_B-1) ========
    if (b < SCAN_B) {
        int i = b * SCAN_T + t;
        int v = (i < NN) ? g_deg[i] : 0;

        // in-place weight conversion (smaxkey final after k_fused)
        if (i < NN) {
            unsigned k = g_smaxkey;
            unsigned bb = (k & 0x80000000u) ? (k ^ 0x80000000u) : ~k;
            float smax = __uint_as_float(bb);
            g_snode[i] = __expf(g_snode[i] - smax);
        }

        int lane = t & 31, wid = t >> 5;
        int inc = v;
#pragma unroll
        for (int o = 1; o < 32; o <<= 1) {
            int u = __shfl_up_sync(0xffffffffu, inc, o);
            if (lane >= o) inc += u;
        }
        __shared__ int wtot[32];
        __shared__ int stotal;
        __shared__ int sprefix;
        if (lane == 31) wtot[wid] = inc;
        __syncthreads();
        if (wid == 0) {
            int s = wtot[lane];
            int sinc = s;
#pragma unroll
            for (int o = 1; o < 32; o <<= 1) {
                int u = __shfl_up_sync(0xffffffffu, sinc, o);
                if (lane >= o) sinc += u;
            }
            wtot[lane] = sinc - s;
            if (lane == 31) stotal = sinc;
        }
        __syncthreads();
        int ex = wtot[wid] + inc - v;
        int total = stotal;

        if (t == 0) {
            if (b == 0) {
                atomicExch(&g_scanstate[0], (2ull << 32) | (unsigned)total);
                sprefix = 0;
            } else {
                atomicExch(&g_scanstate[b], (1ull << 32) | (unsigned)total);
                int prefix = 0;
                for (int j = b - 1; j >= 0;) {
                    unsigned long long st;
                    do { st = atomicAdd(&g_scanstate[j], 0ull); } while ((st >> 32) == 0ull);
                    prefix += (int)(unsigned)st;
                    if ((st >> 32) == 2ull) break;
                    j--;
                }
                atomicExch(&g_scanstate[b], (2ull << 32) | (unsigned)(prefix + total));
                sprefix = prefix;
            }
        }
        __syncthreads();
        int off = sprefix + ex;
        if (i < NN) { g_off[i] = off; g_cur[i] = off; }
        if (b == SCAN_B - 1 && t == 0) g_off[NN] = sprefix + total;  // == EE
    }

    devbar(&g_bar1);

    // ======== Phase B: scatter srcRow into CSR-by-dest + cleanup ===========
    {
        int gtid = b * MID_T + t;
        for (int e = gtid; e < EE; e += MID_STRIDE) {
            int2 rc = __ldg(&g_rc[e]);
            int pos = atomicAdd(&g_cur[rc.y], 1);
            g_eidx[pos] = rc.x;
        }
        // restore zero-invariants for the next graph replay
        for (int i = gtid; i < NN; i += MID_STRIDE) g_deg[i] = 0;
        if (gtid < SCAN_B) g_scanstate[gtid] = 0ull;
        if (gtid == 0) g_smaxkey = 0u;
    }

    devbar(&g_bar2);

    // ======== Phase C: aggregation — 8 lanes/node, 4 nodes/warp ============
    // Lane owns dims 8q..8q+7 exclusively (one fp16 LDG.128 per edge);
    // sumw computed redundantly-identically by the 8 lanes: no shuffles.
    {
        int lane = t & 31;
        int g = lane >> 3;   // node slot within warp
        int q = lane & 7;    // dim octet
        int w0 = (b * MID_T + t) >> 5;
        const int numWarps = MID_STRIDE / 32;  // 4736
        for (int wi = w0; wi < NGROUPS; wi += numWarps) {
            int n = wi * 4 + g;
            int beg = g_off[n], end = g_off[n + 1];
            F2U a0, a1, a2, a3;
            a0.u = a1.u = a2.u = a3.u = 0ull;
            float sumw = 0.f;
#pragma unroll 2
            for (int i = beg; i < end; i++) {
                int row = g_eidx[i];
                float w = g_snode[row];
                sumw += w;
                uint4 hv = *(const uint4*)(g_xh + (size_t)row * 32 + q * 4);
                F2U wp; wp.f2 = make_float2(w, w);
                F2U f0, f1, f2, f3;
                f0.f2 = __half22float2(*(__half2*)&hv.x);
                f1.f2 = __half22float2(*(__half2*)&hv.y);
                f2.f2 = __half22float2(*(__half2*)&hv.z);
                f3.f2 = __half22float2(*(__half2*)&hv.w);
                a0 = ffma2(wp, f0, a0);
                a1 = ffma2(wp, f1, a1);
                a2 = ffma2(wp, f2, a2);
                a3 = ffma2(wp, f3, a3);
            }
            float inv = (sumw > 0.f) ? (1.0f / sumw) : 0.f;
            float* op = g_agg + (size_t)n * DD + q * 8;
            *(float4*)op = make_float4(a0.f2.x * inv, a0.f2.y * inv,
                                       a1.f2.x * inv, a1.f2.y * inv);
            *(float4*)(op + 4) = make_float4(a2.f2.x * inv, a2.f2.y * inv,
                                             a3.f2.x * inv, a3.f2.y * inv);
            if (q == 0) g_has[n] = (sumw > 0.f) ? 1.0f : 0.0f;
        }
    }
}

// ---------------- K3: out = agg@Wm + has*bm + x@Wr + br ---------------------
#define SA_STRIDE 260
__global__ void __launch_bounds__(256, 1) k_out(
    const float* __restrict__ x,
    const float* __restrict__ Wm, const float* __restrict__ bm,
    const float* __restrict__ Wr, const float* __restrict__ br,
    float* __restrict__ out) {
    __shared__ float sAk[32 * SA_STRIDE];  // [k within chunk][node]
    __shared__ float sWs[32 * 64];         // [k within chunk][col]

    int t = threadIdx.x;
    if (blockIdx.x == 0 && t == 0) { g_bar1 = 0; g_bar2 = 0; }  // reset for next replay
    int cg = t & 7;
    int ng = t >> 3;
    int nb0 = blockIdx.x * 256;

    float4 bm0 = __ldg((const float4*)(bm + cg * 8));
    float4 bm1 = __ldg((const float4*)(bm + cg * 8 + 4));
    float4 br0 = __ldg((const float4*)(br + cg * 8));
    float4 br1 = __ldg((const float4*)(br + cg * 8 + 4));

    F2U acc[8][4];
#pragma unroll
    for (int i = 0; i < 8; i++)
#pragma unroll
        for (int p = 0; p < 4; p++) acc[i][p].u = 0ull;

    int node = nb0 + t;
    for (int kc = 0; kc < 4; kc++) {
        const float* Asrc = (kc < 2) ? g_agg : x;
        int koff = (kc < 2) ? kc * 32 : (kc - 2) * 32;
        const float* Wsrc = (kc < 2) ? (Wm + kc * 32 * 64) : (Wr + (kc - 2) * 32 * 64);
        __syncthreads();
        const float4* ap = (const float4*)(Asrc + (size_t)node * DD + koff);
#pragma unroll
        for (int kq = 0; kq < 8; kq++) {
            float4 v = (node < NN) ? __ldg(&ap[kq]) : make_float4(0.f, 0.f, 0.f, 0.f);
            sAk[(kq * 4 + 0) * SA_STRIDE + t] = v.x;
            sAk[(kq * 4 + 1) * SA_STRIDE + t] = v.y;
            sAk[(kq * 4 + 2) * SA_STRIDE + t] = v.z;
            sAk[(kq * 4 + 3) * SA_STRIDE + t] = v.w;
        }
        ((float4*)sWs)[t] = __ldg(&((const float4*)Wsrc)[t]);
        ((float4*)sWs)[t + 256] = __ldg(&((const float4*)Wsrc)[t + 256]);
        __syncthreads();

#pragma unroll 4
        for (int kk = 0; kk < 32; kk++) {
            float4 wa = *(const float4*)&sWs[kk * 64 + cg * 8];
            float4 wb = *(const float4*)&sWs[kk * 64 + cg * 8 + 4];
            F2U w0, w1, w2, w3;
            w0.f2 = make_float2(wa.x, wa.y); w1.f2 = make_float2(wa.z, wa.w);
            w2.f2 = make_float2(wb.x, wb.y); w3.f2 = make_float2(wb.z, wb.w);
            float4 a03 = *(const float4*)&sAk[kk * SA_STRIDE + ng * 8];
            float4 a47 = *(const float4*)&sAk[kk * SA_STRIDE + ng * 8 + 4];
            float av[8] = {a03.x, a03.y, a03.z, a03.w, a47.x, a47.y, a47.z, a47.w};
#pragma unroll
            for (int i = 0; i < 8; i++) {
                F2U ap2; ap2.f2 = make_float2(av[i], av[i]);
                acc[i][0] = ffma2(ap2, w0, acc[i][0]);
                acc[i][1] = ffma2(ap2, w1, acc[i][1]);
                acc[i][2] = ffma2(ap2, w2, acc[i][2]);
                acc[i][3] = ffma2(ap2, w3, acc[i][3]);
            }
        }
    }

#pragma unroll
    for (int i = 0; i < 8; i++) {
        int n = nb0 + ng * 8 + i;
        if (n >= NN) break;
        float h = g_has[n];
        float4 o0 = make_float4(acc[i][0].f2.x + h * bm0.x + br0.x,
                                acc[i][0].f2.y + h * bm0.y + br0.y,
                                acc[i][1].f2.x + h * bm0.z + br0.z,
                                acc[i][1].f2.y + h * bm0.w + br0.w);
        float4 o1 = make_float4(acc[i][2].f2.x + h * bm1.x + br1.x,
                                acc[i][2].f2.y + h * bm1.y + br1.y,
                                acc[i][3].f2.x + h * bm1.z + br1.z,
                                acc[i][3].f2.y + h * bm1.w + br1.w);
        float* op = out + (size_t)n * DD + cg * 8;
        *(float4*)op = o0;
        *(float4*)(op + 4) = o1;
    }
}

// ---------------- launcher ---------------------------------------------------
extern "C" void kernel_launch(void* const* d_in, const int* in_sizes, int n_in,
                              void* d_out, int out_size) {
    const float* x  = (const float*)d_in[0];
    const void*  ei = d_in[1];
    const float* Wm = (const float*)d_in[2];
    const float* bm = (const float*)d_in[3];
    const float* Wr = (const float*)d_in[4];
    const float* br = (const float*)d_in[5];
    float* out = (float*)d_out;

    k_fused<<<EDGE_BLOCKS + SN_BLOCKS, 256>>>(x, ei, Wm, bm);
    k_mid<<<MID_B, MID_T>>>();
    k_out<<<SN_BLOCKS, 256>>>(x, Wm, bm, Wr, br, out);
}

// round 12
// speedup vs baseline: 1.0977x; 1.0977x over previous
#include <cuda_runtime.h>
#include <cuda_fp16.h>

#define NN 100000
#define EE 1600000
#define DD 64
#define SCAN_T 1024
#define SCAN_B 98                  // ceil(NN/1024)
#define EDGE_B4 1563               // ceil(EE/1024): 4 edges/thread blocks
#define SN_BLOCKS 391              // ceil(NN/256)
#define NGROUPS (NN / 4)           // 25000 exact: 4 nodes per warp

// ---------------- scratch (static device globals; zero-init at load) --------
// Invariants at entry: g_deg, g_scanstate, g_smaxkey are ZERO.
// True at load; restored by k_scatter every run (graph replays full sequence).
__device__ unsigned g_smaxkey;
__device__ float    g_snode[NN];             // score, then exp(s-gmax) in-place
__device__ float    g_has[NN];
__device__ int      g_deg[NN];
__device__ int      g_off[NN + 1];
__device__ int      g_cur[NN];
__device__ int2     g_rc[EE];                // interleaved (row, col)
__device__ int      g_eidx[EE];              // CSR-by-dest: srcRow only
__device__ __half2  g_xh[(size_t)NN * 32];   // fp16 mirror of x
__device__ float    g_agg[(size_t)NN * DD];
__device__ unsigned long long g_scanstate[SCAN_B];  // (flag<<32)|value

// ---------------- packed f32x2 FMA (2x fp32 FMA rate on sm_103a) ------------
union F2U { float2 f2; unsigned long long u; };
__device__ __forceinline__ F2U ffma2(F2U a, F2U b, F2U c) {
    F2U d;
    asm("fma.rn.f32x2 %0, %1, %2, %3;" : "=l"(d.u) : "l"(a.u), "l"(b.u), "l"(c.u));
    return d;
}

// ---------------- K1: FUSED (edges, 4/thread) || (scores + fp16 copy) -------
__global__ void __launch_bounds__(256) k_fused(
    const float* __restrict__ x, const void* __restrict__ ei,
    const float* __restrict__ Wm, const float* __restrict__ bm) {
    int b = blockIdx.x;
    int t = threadIdx.x;
    if (b < EDGE_B4) {
        // int64 detection: leading odd 32-bit words all zero <=> int64 ids.
        int2 probe = __ldg(&((const int2*)ei)[t]);
        int any = __syncthreads_or(probe.y);
        int e0 = b * 1024 + t;
        int row[4], col[4];
        if (any == 0) {  // int64
            const long long* p = (const long long*)ei;
#pragma unroll
            for (int k = 0; k < 4; k++) {
                int e = e0 + k * 256;
                if (e < EE) {
                    row[k] = (int)__ldg(&p[e]);
                    col[k] = (int)__ldg(&p[(long long)EE + e]);
                }
            }
        } else {         // int32
            const int* p = (const int*)ei;
#pragma unroll
            for (int k = 0; k < 4; k++) {
                int e = e0 + k * 256;
                if (e < EE) {
                    row[k] = __ldg(&p[e]);
                    col[k] = __ldg(&p[EE + e]);
                }
            }
        }
#pragma unroll
        for (int k = 0; k < 4; k++) {
            int e = e0 + k * 256;
            if (e < EE) {
                g_rc[e] = make_int2(row[k], col[k]);
                atomicAdd(&g_deg[col[k]], 1);
            }
        }
    } else {
        // ---- per-node score s = x[n].wbar + bmean ----
        __shared__ float swb[DD];
        __shared__ float sbm;
        if (t < DD) {
            float s = 0.f;
#pragma unroll
            for (int j = 0; j < DD; j++) s += __ldg(&Wm[t * DD + j]);
            swb[t] = s * (1.0f / DD);
        }
        if (t == 0) {
            float bs = 0.f;
            for (int j = 0; j < DD; j++) bs += __ldg(&bm[j]);
            sbm = bs * (1.0f / DD);
        }
        __syncthreads();
        int n0 = (b - EDGE_B4) * 256;
        int n = n0 + t;
        float s = -1e30f;
        if (n < NN) {
            const float4* xp = (const float4*)(x + (size_t)n * DD);
            float acc = 0.f;
#pragma unroll
            for (int i = 0; i < DD / 4; i++) {
                float4 v = __ldg(&xp[i]);
                acc += v.x * swb[4 * i] + v.y * swb[4 * i + 1] +
                       v.z * swb[4 * i + 2] + v.w * swb[4 * i + 3];
            }
            s = acc + sbm;  // BETA = 1.0
            g_snode[n] = s;
        }
        float m = s;
#pragma unroll
        for (int o = 16; o; o >>= 1) m = fmaxf(m, __shfl_xor_sync(0xffffffffu, m, o));
        if ((t & 31) == 0) {
            unsigned bb = __float_as_uint(m);
            unsigned key = (bb & 0x80000000u) ? ~bb : (bb | 0x80000000u);
            atomicMax(&g_smaxkey, key);
        }
        // ---- fp16 mirror, coalesced ----
        int lim = (NN - n0 < 256) ? (NN - n0) : 256;
        for (int j = t; j < lim * 32; j += 256) {
            int node = n0 + (j >> 5);
            int h = j & 31;
            float2 v = __ldg((const float2*)(x + (size_t)node * DD + 2 * h));
            g_xh[(size_t)node * 32 + h] = __floats2half2_rn(v.x, v.y);
        }
    }
}

// ---------------- K2: decoupled-lookback scan + snode -> exp(s-gmax) --------
__global__ void __launch_bounds__(SCAN_T) k_scan() {
    int b = blockIdx.x, t = threadIdx.x;
    int i = b * SCAN_T + t;
    int v = (i < NN) ? g_deg[i] : 0;

    if (i < NN) {
        unsigned k = g_smaxkey;
        unsigned bb = (k & 0x80000000u) ? (k ^ 0x80000000u) : ~k;
        float smax = __uint_as_float(bb);
        g_snode[i] = __expf(g_snode[i] - smax);
    }

    int lane = t & 31, wid = t >> 5;
    int inc = v;
#pragma unroll
    for (int o = 1; o < 32; o <<= 1) {
        int u = __shfl_up_sync(0xffffffffu, inc, o);
        if (lane >= o) inc += u;
    }
    __shared__ int wtot[32];
    __shared__ int stotal;
    __shared__ int sprefix;
    if (lane == 31) wtot[wid] = inc;
    __syncthreads();
    if (wid == 0) {
        int s = wtot[lane];
        int sinc = s;
#pragma unroll
        for (int o = 1; o < 32; o <<= 1) {
            int u = __shfl_up_sync(0xffffffffu, sinc, o);
            if (lane >= o) sinc += u;
        }
        wtot[lane] = sinc - s;
        if (lane == 31) stotal = sinc;
    }
    __syncthreads();
    int ex = wtot[wid] + inc - v;
    int total = stotal;

    if (t == 0) {
        if (b == 0) {
            atomicExch(&g_scanstate[0], (2ull << 32) | (unsigned)total);
            sprefix = 0;
        } else {
            atomicExch(&g_scanstate[b], (1ull << 32) | (unsigned)total);
            int prefix = 0;
            for (int j = b - 1; j >= 0;) {
                unsigned long long st;
                do { st = atomicAdd(&g_scanstate[j], 0ull); } while ((st >> 32) == 0ull);
                prefix += (int)(unsigned)st;
                if ((st >> 32) == 2ull) break;
                j--;
            }
            atomicExch(&g_scanstate[b], (2ull << 32) | (unsigned)(prefix + total));
            sprefix = prefix;
        }
    }
    __syncthreads();
    int off = sprefix + ex;
    if (i < NN) { g_off[i] = off; g_cur[i] = off; }
    if (b == SCAN_B - 1 && t == 0) g_off[NN] = sprefix + total;  // == EE
}

// ---------------- K3: scatter srcRow into CSR-by-dest + cleanup -------------
__global__ void __launch_bounds__(256) k_scatter() {
    int e0 = blockIdx.x * 1024 + threadIdx.x;
#pragma unroll
    for (int k = 0; k < 4; k++) {
        int e = e0 + k * 256;
        if (e < EE) {
            int2 rc = __ldg(&g_rc[e]);
            int pos = atomicAdd(&g_cur[rc.y], 1);
            g_eidx[pos] = rc.x;
        }
    }
    // restore zero-invariants for the next graph replay
    int gtid = blockIdx.x * 256 + threadIdx.x;
    for (int i = gtid; i < NN; i += EDGE_B4 * 256) g_deg[i] = 0;
    if (gtid < SCAN_B) g_scanstate[gtid] = 0ull;
    if (gtid == 0) g_smaxkey = 0u;
}

// ---------------- K4: aggregation — 8 lanes/node, 4 nodes/warp, no shuffles -
// Lane owns dims 8q..8q+7 exclusively (one fp16 LDG.128 per edge); sumw is
// computed redundantly-identically by the 8 lanes of a group.
__global__ void __launch_bounds__(256) k_agg() {
    int wi = (blockIdx.x * blockDim.x + threadIdx.x) >> 5;  // warp id
    int lane = threadIdx.x & 31;
    if (wi >= NGROUPS) return;
    int g = lane >> 3;   // node slot within warp
    int q = lane & 7;    // dim octet
    int n = wi * 4 + g;
    int beg = g_off[n], end = g_off[n + 1];

    F2U a0, a1, a2, a3;
    a0.u = a1.u = a2.u = a3.u = 0ull;
    float sumw = 0.f;
#pragma unroll 2
    for (int i = beg; i < end; i++) {
        int row = __ldg(&g_eidx[i]);
        float w = __ldg(&g_snode[row]);
        sumw += w;
        uint4 hv = __ldg((const uint4*)(g_xh + (size_t)row * 32 + q * 4));
        F2U wp; wp.f2 = make_float2(w, w);
        F2U f0, f1, f2, f3;
        f0.f2 = __half22float2(*(__half2*)&hv.x);
        f1.f2 = __half22float2(*(__half2*)&hv.y);
        f2.f2 = __half22float2(*(__half2*)&hv.z);
        f3.f2 = __half22float2(*(__half2*)&hv.w);
        a0 = ffma2(wp, f0, a0);
        a1 = ffma2(wp, f1, a1);
        a2 = ffma2(wp, f2, a2);
        a3 = ffma2(wp, f3, a3);
    }
    float inv = (sumw > 0.f) ? (1.0f / sumw) : 0.f;
    float* op = g_agg + (size_t)n * DD + q * 8;
    *(float4*)op = make_float4(a0.f2.x * inv, a0.f2.y * inv,
                               a1.f2.x * inv, a1.f2.y * inv);
    *(float4*)(op + 4) = make_float4(a2.f2.x * inv, a2.f2.y * inv,
                                     a3.f2.x * inv, a3.f2.y * inv);
    if (q == 0) g_has[n] = (sumw > 0.f) ? 1.0f : 0.0f;
}

// ---------------- K5: out = agg@Wm + has*bm + x@Wr + br ---------------------
#define SA_STRIDE 260
__global__ void __launch_bounds__(256, 1) k_out(
    const float* __restrict__ x,
    const float* __restrict__ Wm, const float* __restrict__ bm,
    const float* __restrict__ Wr, const float* __restrict__ br,
    float* __restrict__ out) {
    __shared__ float sAk[32 * SA_STRIDE];  // [k within chunk][node]
    __shared__ float sWs[32 * 64];         // [k within chunk][col]

    int t = threadIdx.x;
    int cg = t & 7;
    int ng = t >> 3;
    int nb0 = blockIdx.x * 256;

    float4 bm0 = __ldg((const float4*)(bm + cg * 8));
    float4 bm1 = __ldg((const float4*)(bm + cg * 8 + 4));
    float4 br0 = __ldg((const float4*)(br + cg * 8));
    float4 br1 = __ldg((const float4*)(br + cg * 8 + 4));

    F2U acc[8][4];
#pragma unroll
    for (int i = 0; i < 8; i++)
#pragma unroll
        for (int p = 0; p < 4; p++) acc[i][p].u = 0ull;

    int node = nb0 + t;
    for (int kc = 0; kc < 4; kc++) {
        const float* Asrc = (kc < 2) ? g_agg : x;
        int koff = (kc < 2) ? kc * 32 : (kc - 2) * 32;
        const float* Wsrc = (kc < 2) ? (Wm + kc * 32 * 64) : (Wr + (kc - 2) * 32 * 64);
        __syncthreads();
        const float4* ap = (const float4*)(Asrc + (size_t)node * DD + koff);
#pragma unroll
        for (int kq = 0; kq < 8; kq++) {
            float4 v = (node < NN) ? __ldg(&ap[kq]) : make_float4(0.f, 0.f, 0.f, 0.f);
            sAk[(kq * 4 + 0) * SA_STRIDE + t] = v.x;
            sAk[(kq * 4 + 1) * SA_STRIDE + t] = v.y;
            sAk[(kq * 4 + 2) * SA_STRIDE + t] = v.z;
            sAk[(kq * 4 + 3) * SA_STRIDE + t] = v.w;
        }
        ((float4*)sWs)[t] = __ldg(&((const float4*)Wsrc)[t]);
        ((float4*)sWs)[t + 256] = __ldg(&((const float4*)Wsrc)[t + 256]);
        __syncthreads();

#pragma unroll 4
        for (int kk = 0; kk < 32; kk++) {
            float4 wa = *(const float4*)&sWs[kk * 64 + cg * 8];
            float4 wb = *(const float4*)&sWs[kk * 64 + cg * 8 + 4];
            F2U w0, w1, w2, w3;
            w0.f2 = make_float2(wa.x, wa.y); w1.f2 = make_float2(wa.z, wa.w);
            w2.f2 = make_float2(wb.x, wb.y); w3.f2 = make_float2(wb.z, wb.w);
            float4 a03 = *(const float4*)&sAk[kk * SA_STRIDE + ng * 8];
            float4 a47 = *(const float4*)&sAk[kk * SA_STRIDE + ng * 8 + 4];
            float av[8] = {a03.x, a03.y, a03.z, a03.w, a47.x, a47.y, a47.z, a47.w};
#pragma unroll
            for (int i = 0; i < 8; i++) {
                F2U ap2; ap2.f2 = make_float2(av[i], av[i]);
                acc[i][0] = ffma2(ap2, w0, acc[i][0]);
                acc[i][1] = ffma2(ap2, w1, acc[i][1]);
                acc[i][2] = ffma2(ap2, w2, acc[i][2]);
                acc[i][3] = ffma2(ap2, w3, acc[i][3]);
            }
        }
    }

#pragma unroll
    for (int i = 0; i < 8; i++) {
        int n = nb0 + ng * 8 + i;
        if (n >= NN) break;
        float h = g_has[n];
        float4 o0 = make_float4(acc[i][0].f2.x + h * bm0.x + br0.x,
                                acc[i][0].f2.y + h * bm0.y + br0.y,
                                acc[i][1].f2.x + h * bm0.z + br0.z,
                                acc[i][1].f2.y + h * bm0.w + br0.w);
        float4 o1 = make_float4(acc[i][2].f2.x + h * bm1.x + br1.x,
                                acc[i][2].f2.y + h * bm1.y + br1.y,
                                acc[i][3].f2.x + h * bm1.z + br1.z,
                                acc[i][3].f2.y + h * bm1.w + br1.w);
        float* op = out + (size_t)n * DD + cg * 8;
        *(float4*)op = o0;
        *(float4*)(op + 4) = o1;
    }
}

// ---------------- launcher ---------------------------------------------------
extern "C" void kernel_launch(void* const* d_in, const int* in_sizes, int n_in,
                              void* d_out, int out_size) {
    const float* x  = (const float*)d_in[0];
    const void*  ei = d_in[1];
    const float* Wm = (const float*)d_in[2];
    const float* bm = (const float*)d_in[3];
    const float* Wr = (const float*)d_in[4];
    const float* br = (const float*)d_in[5];
    float* out = (float*)d_out;

    k_fused<<<EDGE_B4 + SN_BLOCKS, 256>>>(x, ei, Wm, bm);
    k_scan<<<SCAN_B, SCAN_T>>>();
    k_scatter<<<EDGE_B4, 256>>>();
    k_agg<<<(NGROUPS * 32 + 255) / 256, 256>>>();
    k_out<<<SN_BLOCKS, 256>>>(x, Wm, bm, Wr, br, out);
}

// round 13
// speedup vs baseline: 1.1095x; 1.0107x over previous
#include <cuda_runtime.h>
#include <cuda_fp16.h>

#define NN 100000
#define EE 1600000
#define DD 64
#define SCAN_T 1024
#define SCAN_B 98                  // ceil(NN/1024)
#define EDGE_B8 782                // ceil(EE/2048): 8 edges/thread blocks
#define SN_BLOCKS 391              // ceil(NN/256)
#define NGROUPS (NN / 4)           // 25000 exact: 4 nodes per warp

// ---------------- scratch (static device globals; zero-init at load) --------
// Invariants at entry: g_deg, g_scanstate, g_smaxkey are ZERO.
// True at load; restored by k_scatter every run (graph replays full sequence).
__device__ unsigned g_smaxkey;
__device__ float    g_snode[NN];             // score, then exp(s-gmax) in-place
__device__ float    g_has[NN];
__device__ int      g_deg[NN];
__device__ int      g_off[NN + 1];
__device__ int      g_cur[NN];
__device__ int2     g_rc[EE];                // interleaved (row, col)
__device__ int2     g_edge[EE];              // CSR-by-dest: (srcRow, bits(w))
__device__ __half2  g_xh[(size_t)NN * 32];   // fp16 mirror of x
__device__ float    g_agg[(size_t)NN * DD];
__device__ unsigned long long g_scanstate[SCAN_B];  // (flag<<32)|value

// ---------------- packed f32x2 FMA (2x fp32 FMA rate on sm_103a) ------------
union F2U { float2 f2; unsigned long long u; };
__device__ __forceinline__ F2U ffma2(F2U a, F2U b, F2U c) {
    F2U d;
    asm("fma.rn.f32x2 %0, %1, %2, %3;" : "=l"(d.u) : "l"(a.u), "l"(b.u), "l"(c.u));
    return d;
}

// ---------------- K1: FUSED (edges, 8/thread) || (scores + fp16 copy) -------
__global__ void __launch_bounds__(256) k_fused(
    const float* __restrict__ x, const void* __restrict__ ei,
    const float* __restrict__ Wm, const float* __restrict__ bm) {
    int b = blockIdx.x;
    int t = threadIdx.x;
    if (b < EDGE_B8) {
        // int64 detection: leading odd 32-bit words all zero <=> int64 ids.
        int2 probe = __ldg(&((const int2*)ei)[t]);
        int any = __syncthreads_or(probe.y);
        int e0 = b * 2048 + t;
        int row[8], col[8];
        if (any == 0) {  // int64
            const long long* p = (const long long*)ei;
#pragma unroll
            for (int k = 0; k < 8; k++) {
                int e = e0 + k * 256;
                if (e < EE) {
                    row[k] = (int)__ldg(&p[e]);
                    col[k] = (int)__ldg(&p[(long long)EE + e]);
                }
            }
        } else {         // int32
            const int* p = (const int*)ei;
#pragma unroll
            for (int k = 0; k < 8; k++) {
                int e = e0 + k * 256;
                if (e < EE) {
                    row[k] = __ldg(&p[e]);
                    col[k] = __ldg(&p[EE + e]);
                }
            }
        }
#pragma unroll
        for (int k = 0; k < 8; k++) {
            int e = e0 + k * 256;
            if (e < EE) {
                g_rc[e] = make_int2(row[k], col[k]);
                atomicAdd(&g_deg[col[k]], 1);
            }
        }
    } else {
        // ---- per-node score s = x[n].wbar + bmean ----
        __shared__ float swb[DD];
        __shared__ float sbm;
        if (t < DD) {
            float s = 0.f;
#pragma unroll
            for (int j = 0; j < DD; j++) s += __ldg(&Wm[t * DD + j]);
            swb[t] = s * (1.0f / DD);
        }
        if (t == 0) {
            float bs = 0.f;
            for (int j = 0; j < DD; j++) bs += __ldg(&bm[j]);
            sbm = bs * (1.0f / DD);
        }
        __syncthreads();
        int n0 = (b - EDGE_B8) * 256;
        int n = n0 + t;
        float s = -1e30f;
        if (n < NN) {
            const float4* xp = (const float4*)(x + (size_t)n * DD);
            float acc = 0.f;
#pragma unroll
            for (int i = 0; i < DD / 4; i++) {
                float4 v = __ldg(&xp[i]);
                acc += v.x * swb[4 * i] + v.y * swb[4 * i + 1] +
                       v.z * swb[4 * i + 2] + v.w * swb[4 * i + 3];
            }
            s = acc + sbm;  // BETA = 1.0
            g_snode[n] = s;
        }
        float m = s;
#pragma unroll
        for (int o = 16; o; o >>= 1) m = fmaxf(m, __shfl_xor_sync(0xffffffffu, m, o));
        if ((t & 31) == 0) {
            unsigned bb = __float_as_uint(m);
            unsigned key = (bb & 0x80000000u) ? ~bb : (bb | 0x80000000u);
            atomicMax(&g_smaxkey, key);
        }
        // ---- fp16 mirror, coalesced ----
        int lim = (NN - n0 < 256) ? (NN - n0) : 256;
        for (int j = t; j < lim * 32; j += 256) {
            int node = n0 + (j >> 5);
            int h = j & 31;
            float2 v = __ldg((const float2*)(x + (size_t)node * DD + 2 * h));
            g_xh[(size_t)node * 32 + h] = __floats2half2_rn(v.x, v.y);
        }
    }
}

// ---------------- K2: decoupled-lookback scan + snode -> exp(s-gmax) --------
__global__ void __launch_bounds__(SCAN_T) k_scan() {
    int b = blockIdx.x, t = threadIdx.x;
    int i = b * SCAN_T + t;
    int v = (i < NN) ? g_deg[i] : 0;

    if (i < NN) {
        unsigned k = g_smaxkey;
        unsigned bb = (k & 0x80000000u) ? (k ^ 0x80000000u) : ~k;
        float smax = __uint_as_float(bb);
        g_snode[i] = __expf(g_snode[i] - smax);
    }

    int lane = t & 31, wid = t >> 5;
    int inc = v;
#pragma unroll
    for (int o = 1; o < 32; o <<= 1) {
        int u = __shfl_up_sync(0xffffffffu, inc, o);
        if (lane >= o) inc += u;
    }
    __shared__ int wtot[32];
    __shared__ int stotal;
    __shared__ int sprefix;
    if (lane == 31) wtot[wid] = inc;
    __syncthreads();
    if (wid == 0) {
        int s = wtot[lane];
        int sinc = s;
#pragma unroll
        for (int o = 1; o < 32; o <<= 1) {
            int u = __shfl_up_sync(0xffffffffu, sinc, o);
            if (lane >= o) sinc += u;
        }
        wtot[lane] = sinc - s;
        if (lane == 31) stotal = sinc;
    }
    __syncthreads();
    int ex = wtot[wid] + inc - v;
    int total = stotal;

    if (t == 0) {
        if (b == 0) {
            atomicExch(&g_scanstate[0], (2ull << 32) | (unsigned)total);
            sprefix = 0;
        } else {
            atomicExch(&g_scanstate[b], (1ull << 32) | (unsigned)total);
            int prefix = 0;
            for (int j = b - 1; j >= 0;) {
                unsigned long long st;
                do { st = atomicAdd(&g_scanstate[j], 0ull); } while ((st >> 32) == 0ull);
                prefix += (int)(unsigned)st;
                if ((st >> 32) == 2ull) break;
                j--;
            }
            atomicExch(&g_scanstate[b], (2ull << 32) | (unsigned)(prefix + total));
            sprefix = prefix;
        }
    }
    __syncthreads();
    int off = sprefix + ex;
    if (i < NN) { g_off[i] = off; g_cur[i] = off; }
    if (b == SCAN_B - 1 && t == 0) g_off[NN] = sprefix + total;  // == EE
}

// ---------------- K3: scatter (srcRow, w) into CSR-by-dest + cleanup --------
__global__ void __launch_bounds__(256) k_scatter() {
    int e0 = blockIdx.x * 2048 + threadIdx.x;
#pragma unroll
    for (int k = 0; k < 8; k++) {
        int e = e0 + k * 256;
        if (e < EE) {
            int2 rc = __ldg(&g_rc[e]);
            float w = __ldg(&g_snode[rc.x]);
            int pos = atomicAdd(&g_cur[rc.y], 1);
            g_edge[pos] = make_int2(rc.x, __float_as_int(w));
        }
    }
    // restore zero-invariants for the next graph replay
    int gtid = blockIdx.x * 256 + threadIdx.x;
    for (int i = gtid; i < NN; i += EDGE_B8 * 256) g_deg[i] = 0;
    if (gtid < SCAN_B) g_scanstate[gtid] = 0ull;
    if (gtid == 0) g_smaxkey = 0u;
}

// ---------------- K4: aggregation — 8 lanes/node, 4 nodes/warp, no shuffles -
// Lane owns dims 8q..8q+7 (one fp16 LDG.128 per edge). Edge record carries
// (row, w): no dependent snode gather. sumw computed redundantly by 8 lanes.
__global__ void __launch_bounds__(256) k_agg() {
    int wi = (blockIdx.x * blockDim.x + threadIdx.x) >> 5;  // warp id
    int lane = threadIdx.x & 31;
    if (wi >= NGROUPS) return;
    int g = lane >> 3;   // node slot within warp
    int q = lane & 7;    // dim octet
    int n = wi * 4 + g;
    int beg = g_off[n], end = g_off[n + 1];

    F2U a0, a1, a2, a3;
    a0.u = a1.u = a2.u = a3.u = 0ull;
    float sumw = 0.f;
#pragma unroll 2
    for (int i = beg; i < end; i++) {
        int2 ed = __ldg(&g_edge[i]);
        float w = __int_as_float(ed.y);
        sumw += w;
        uint4 hv = __ldg((const uint4*)(g_xh + (size_t)ed.x * 32 + q * 4));
        F2U wp; wp.f2 = make_float2(w, w);
        F2U f0, f1, f2, f3;
        f0.f2 = __half22float2(*(__half2*)&hv.x);
        f1.f2 = __half22float2(*(__half2*)&hv.y);
        f2.f2 = __half22float2(*(__half2*)&hv.z);
        f3.f2 = __half22float2(*(__half2*)&hv.w);
        a0 = ffma2(wp, f0, a0);
        a1 = ffma2(wp, f1, a1);
        a2 = ffma2(wp, f2, a2);
        a3 = ffma2(wp, f3, a3);
    }
    float inv = (sumw > 0.f) ? (1.0f / sumw) : 0.f;
    float* op = g_agg + (size_t)n * DD + q * 8;
    *(float4*)op = make_float4(a0.f2.x * inv, a0.f2.y * inv,
                               a1.f2.x * inv, a1.f2.y * inv);
    *(float4*)(op + 4) = make_float4(a2.f2.x * inv, a2.f2.y * inv,
                                     a3.f2.x * inv, a3.f2.y * inv);
    if (q == 0) g_has[n] = (sumw > 0.f) ? 1.0f : 0.0f;
}

// ---------------- K5: out = agg@Wm + has*bm + x@Wr + br ---------------------
#define SA_STRIDE 260
__global__ void __launch_bounds__(256, 1) k_out(
    const float* __restrict__ x,
    const float* __restrict__ Wm, const float* __restrict__ bm,
    const float* __restrict__ Wr, const float* __restrict__ br,
    float* __restrict__ out) {
    __shared__ float sAk[32 * SA_STRIDE];  // [k within chunk][node]
    __shared__ float sWs[32 * 64];         // [k within chunk][col]

    int t = threadIdx.x;
    int cg = t & 7;
    int ng = t >> 3;
    int nb0 = blockIdx.x * 256;

    float4 bm0 = __ldg((const float4*)(bm + cg * 8));
    float4 bm1 = __ldg((const float4*)(bm + cg * 8 + 4));
    float4 br0 = __ldg((const float4*)(br + cg * 8));
    float4 br1 = __ldg((const float4*)(br + cg * 8 + 4));

    F2U acc[8][4];
#pragma unroll
    for (int i = 0; i < 8; i++)
#pragma unroll
        for (int p = 0; p < 4; p++) acc[i][p].u = 0ull;

    int node = nb0 + t;
    for (int kc = 0; kc < 4; kc++) {
        const float* Asrc = (kc < 2) ? g_agg : x;
        int koff = (kc < 2) ? kc * 32 : (kc - 2) * 32;
        const float* Wsrc = (kc < 2) ? (Wm + kc * 32 * 64) : (Wr + (kc - 2) * 32 * 64);
        __syncthreads();
        const float4* ap = (const float4*)(Asrc + (size_t)node * DD + koff);
#pragma unroll
        for (int kq = 0; kq < 8; kq++) {
            float4 v = (node < NN) ? __ldg(&ap[kq]) : make_float4(0.f, 0.f, 0.f, 0.f);
            sAk[(kq * 4 + 0) * SA_STRIDE + t] = v.x;
            sAk[(kq * 4 + 1) * SA_STRIDE + t] = v.y;
            sAk[(kq * 4 + 2) * SA_STRIDE + t] = v.z;
            sAk[(kq * 4 + 3) * SA_STRIDE + t] = v.w;
        }
        ((float4*)sWs)[t] = __ldg(&((const float4*)Wsrc)[t]);
        ((float4*)sWs)[t + 256] = __ldg(&((const float4*)Wsrc)[t + 256]);
        __syncthreads();

#pragma unroll 4
        for (int kk = 0; kk < 32; kk++) {
            float4 wa = *(const float4*)&sWs[kk * 64 + cg * 8];
            float4 wb = *(const float4*)&sWs[kk * 64 + cg * 8 + 4];
            F2U w0, w1, w2, w3;
            w0.f2 = make_float2(wa.x, wa.y); w1.f2 = make_float2(wa.z, wa.w);
            w2.f2 = make_float2(wb.x, wb.y); w3.f2 = make_float2(wb.z, wb.w);
            float4 a03 = *(const float4*)&sAk[kk * SA_STRIDE + ng * 8];
            float4 a47 = *(const float4*)&sAk[kk * SA_STRIDE + ng * 8 + 4];
            float av[8] = {a03.x, a03.y, a03.z, a03.w, a47.x, a47.y, a47.z, a47.w};
#pragma unroll
            for (int i = 0; i < 8; i++) {
                F2U ap2; ap2.f2 = make_float2(av[i], av[i]);
                acc[i][0] = ffma2(ap2, w0, acc[i][0]);
                acc[i][1] = ffma2(ap2, w1, acc[i][1]);
                acc[i][2] = ffma2(ap2, w2, acc[i][2]);
                acc[i][3] = ffma2(ap2, w3, acc[i][3]);
            }
        }
    }

#pragma unroll
    for (int i = 0; i < 8; i++) {
        int n = nb0 + ng * 8 + i;
        if (n >= NN) break;
        float h = g_has[n];
        float4 o0 = make_float4(acc[i][0].f2.x + h * bm0.x + br0.x,
                                acc[i][0].f2.y + h * bm0.y + br0.y,
                                acc[i][1].f2.x + h * bm0.z + br0.z,
                                acc[i][1].f2.y + h * bm0.w + br0.w);
        float4 o1 = make_float4(acc[i][2].f2.x + h * bm1.x + br1.x,
                                acc[i][2].f2.y + h * bm1.y + br1.y,
                                acc[i][3].f2.x + h * bm1.z + br1.z,
                                acc[i][3].f2.y + h * bm1.w + br1.w);
        float* op = out + (size_t)n * DD + cg * 8;
        *(float4*)op = o0;
        *(float4*)(op + 4) = o1;
    }
}

// ---------------- launcher ---------------------------------------------------
extern "C" void kernel_launch(void* const* d_in, const int* in_sizes, int n_in,
                              void* d_out, int out_size) {
    const float* x  = (const float*)d_in[0];
    const void*  ei = d_in[1];
    const float* Wm = (const float*)d_in[2];
    const float* bm = (const float*)d_in[3];
    const float* Wr = (const float*)d_in[4];
    const float* br = (const float*)d_in[5];
    float* out = (float*)d_out;

    k_fused<<<EDGE_B8 + SN_BLOCKS, 256>>>(x, ei, Wm, bm);
    k_scan<<<SCAN_B, SCAN_T>>>();
    k_scatter<<<EDGE_B8, 256>>>();
    k_agg<<<(NGROUPS * 32 + 255) / 256, 256>>>();
    k_out<<<SN_BLOCKS, 256>>>(x, Wm, bm, Wr, br, out);
}

// round 14
// speedup vs baseline: 1.1198x; 1.0093x over previous
#include <cuda_runtime.h>
#include <cuda_fp16.h>

#define NN 100000
#define EE 1600000
#define DD 64
#define SCAN_T 1024
#define SCAN_B 98                  // ceil(NN/1024)
#define EDGE_B8 782                // ceil(EE/2048): 8 edges/thread blocks
#define SN_BLOCKS 391              // ceil(NN/256)
#define NGROUPS (NN / 4)           // 25000 exact: 4 nodes per warp

// ---------------- scratch (static device globals; zero-init at load) --------
// Invariants at entry: g_deg, g_scanstate, g_smaxkey are ZERO.
// True at load; restored by k_scatter every run (graph replays full sequence).
__device__ unsigned g_smaxkey;
__device__ float    g_snode[NN];             // score, then exp(s-gmax) in-place
__device__ float    g_has[NN];
__device__ int      g_deg[NN];
__device__ int      g_off[NN + 1];
__device__ int      g_cur[NN];
__device__ int2     g_rc[EE];                // interleaved (row, col)
__device__ int2     g_edge[EE];              // CSR-by-dest: (srcRow, bits(w))
__device__ __half2  g_xh[(size_t)NN * 32];   // fp16 mirror of x
__device__ float    g_agg[(size_t)NN * DD];
__device__ unsigned long long g_scanstate[SCAN_B];  // (flag<<32)|value

// ---------------- packed f32x2 FMA (2x fp32 FMA rate on sm_103a) ------------
union F2U { float2 f2; unsigned long long u; };
__device__ __forceinline__ F2U ffma2(F2U a, F2U b, F2U c) {
    F2U d;
    asm("fma.rn.f32x2 %0, %1, %2, %3;" : "=l"(d.u) : "l"(a.u), "l"(b.u), "l"(c.u));
    return d;
}

// ---------------- K1: FUSED (edges, 8/thread) || (scores + fp16 copy) -------
__global__ void __launch_bounds__(256) k_fused(
    const float* __restrict__ x, const void* __restrict__ ei,
    const float* __restrict__ Wm, const float* __restrict__ bm) {
    int b = blockIdx.x;
    int t = threadIdx.x;
    if (b < EDGE_B8) {
        // int64 detection: leading odd 32-bit words all zero <=> int64 ids.
        int2 probe = __ldg(&((const int2*)ei)[t]);
        int any = __syncthreads_or(probe.y);
        int e0 = b * 2048 + t;
        int row[8], col[8];
        if (any == 0) {  // int64
            const long long* p = (const long long*)ei;
#pragma unroll
            for (int k = 0; k < 8; k++) {
                int e = e0 + k * 256;
                if (e < EE) {
                    row[k] = (int)__ldg(&p[e]);
                    col[k] = (int)__ldg(&p[(long long)EE + e]);
                }
            }
        } else {         // int32
            const int* p = (const int*)ei;
#pragma unroll
            for (int k = 0; k < 8; k++) {
                int e = e0 + k * 256;
                if (e < EE) {
                    row[k] = __ldg(&p[e]);
                    col[k] = __ldg(&p[EE + e]);
                }
            }
        }
#pragma unroll
        for (int k = 0; k < 8; k++) {
            int e = e0 + k * 256;
            if (e < EE) {
                g_rc[e] = make_int2(row[k], col[k]);
                atomicAdd(&g_deg[col[k]], 1);
            }
        }
    } else {
        // ---- per-node score s = x[n].wbar + bmean ----
        __shared__ float swb[DD];
        __shared__ float sbm;
        if (t < DD) {
            float s = 0.f;
#pragma unroll
            for (int j = 0; j < DD; j++) s += __ldg(&Wm[t * DD + j]);
            swb[t] = s * (1.0f / DD);
        }
        if (t == 0) {
            float bs = 0.f;
            for (int j = 0; j < DD; j++) bs += __ldg(&bm[j]);
            sbm = bs * (1.0f / DD);
        }
        __syncthreads();
        int n0 = (b - EDGE_B8) * 256;
        int n = n0 + t;
        float s = -1e30f;
        if (n < NN) {
            const float4* xp = (const float4*)(x + (size_t)n * DD);
            float acc = 0.f;
#pragma unroll
            for (int i = 0; i < DD / 4; i++) {
                float4 v = __ldg(&xp[i]);
                acc += v.x * swb[4 * i] + v.y * swb[4 * i + 1] +
                       v.z * swb[4 * i + 2] + v.w * swb[4 * i + 3];
            }
            s = acc + sbm;  // BETA = 1.0
            g_snode[n] = s;
        }
        float m = s;
#pragma unroll
        for (int o = 16; o; o >>= 1) m = fmaxf(m, __shfl_xor_sync(0xffffffffu, m, o));
        if ((t & 31) == 0) {
            unsigned bb = __float_as_uint(m);
            unsigned key = (bb & 0x80000000u) ? ~bb : (bb | 0x80000000u);
            atomicMax(&g_smaxkey, key);
        }
        // ---- fp16 mirror, coalesced ----
        int lim = (NN - n0 < 256) ? (NN - n0) : 256;
        for (int j = t; j < lim * 32; j += 256) {
            int node = n0 + (j >> 5);
            int h = j & 31;
            float2 v = __ldg((const float2*)(x + (size_t)node * DD + 2 * h));
            g_xh[(size_t)node * 32 + h] = __floats2half2_rn(v.x, v.y);
        }
    }
}

// ---------------- K2: decoupled-lookback scan + snode -> exp(s-gmax) --------
__global__ void __launch_bounds__(SCAN_T) k_scan() {
    cudaGridDependencySynchronize();  // PDL: wait for k_fused results
    int b = blockIdx.x, t = threadIdx.x;
    int i = b * SCAN_T + t;
    int v = (i < NN) ? g_deg[i] : 0;

    if (i < NN) {
        unsigned k = g_smaxkey;
        unsigned bb = (k & 0x80000000u) ? (k ^ 0x80000000u) : ~k;
        float smax = __uint_as_float(bb);
        g_snode[i] = __expf(g_snode[i] - smax);
    }

    int lane = t & 31, wid = t >> 5;
    int inc = v;
#pragma unroll
    for (int o = 1; o < 32; o <<= 1) {
        int u = __shfl_up_sync(0xffffffffu, inc, o);
        if (lane >= o) inc += u;
    }
    __shared__ int wtot[32];
    __shared__ int stotal;
    __shared__ int sprefix;
    if (lane == 31) wtot[wid] = inc;
    __syncthreads();
    if (wid == 0) {
        int s = wtot[lane];
        int sinc = s;
#pragma unroll
        for (int o = 1; o < 32; o <<= 1) {
            int u = __shfl_up_sync(0xffffffffu, sinc, o);
            if (lane >= o) sinc += u;
        }
        wtot[lane] = sinc - s;
        if (lane == 31) stotal = sinc;
    }
    __syncthreads();
    int ex = wtot[wid] + inc - v;
    int total = stotal;

    if (t == 0) {
        if (b == 0) {
            atomicExch(&g_scanstate[0], (2ull << 32) | (unsigned)total);
            sprefix = 0;
        } else {
            atomicExch(&g_scanstate[b], (1ull << 32) | (unsigned)total);
            int prefix = 0;
            for (int j = b - 1; j >= 0;) {
                unsigned long long st;
                do { st = atomicAdd(&g_scanstate[j], 0ull); } while ((st >> 32) == 0ull);
                prefix += (int)(unsigned)st;
                if ((st >> 32) == 2ull) break;
                j--;
            }
            atomicExch(&g_scanstate[b], (2ull << 32) | (unsigned)(prefix + total));
            sprefix = prefix;
        }
    }
    __syncthreads();
    int off = sprefix + ex;
    if (i < NN) { g_off[i] = off; g_cur[i] = off; }
    if (b == SCAN_B - 1 && t == 0) g_off[NN] = sprefix + total;  // == EE
}

// ---------------- K3: scatter (srcRow, w) into CSR-by-dest + cleanup --------
__global__ void __launch_bounds__(256) k_scatter() {
    cudaGridDependencySynchronize();  // PDL: wait for k_scan results
    int e0 = blockIdx.x * 2048 + threadIdx.x;
#pragma unroll
    for (int k = 0; k < 8; k++) {
        int e = e0 + k * 256;
        if (e < EE) {
            int2 rc = __ldg(&g_rc[e]);
            float w = __ldg(&g_snode[rc.x]);
            int pos = atomicAdd(&g_cur[rc.y], 1);
            g_edge[pos] = make_int2(rc.x, __float_as_int(w));
        }
    }
    // restore zero-invariants for the next graph replay
    int gtid = blockIdx.x * 256 + threadIdx.x;
    for (int i = gtid; i < NN; i += EDGE_B8 * 256) g_deg[i] = 0;
    if (gtid < SCAN_B) g_scanstate[gtid] = 0ull;
    if (gtid == 0) g_smaxkey = 0u;
}

// ---------------- K4: aggregation — 8 lanes/node, 4 nodes/warp, no shuffles -
// Lane owns dims 8q..8q+7 (one fp16 LDG.128 per edge). Edge record carries
// (row, w). Latency-bound: unroll 4 for 4 independent gather chains in flight.
__global__ void __launch_bounds__(256) k_agg() {
    cudaGridDependencySynchronize();  // PDL: wait for k_scatter results
    int wi = (blockIdx.x * blockDim.x + threadIdx.x) >> 5;  // warp id
    int lane = threadIdx.x & 31;
    if (wi >= NGROUPS) return;
    int g = lane >> 3;   // node slot within warp
    int q = lane & 7;    // dim octet
    int n = wi * 4 + g;
    int beg = g_off[n], end = g_off[n + 1];

    F2U a0, a1, a2, a3;
    a0.u = a1.u = a2.u = a3.u = 0ull;
    float sumw = 0.f;
#pragma unroll 4
    for (int i = beg; i < end; i++) {
        int2 ed = __ldg(&g_edge[i]);
        float w = __int_as_float(ed.y);
        sumw += w;
        uint4 hv = __ldg((const uint4*)(g_xh + (size_t)ed.x * 32 + q * 4));
        F2U wp; wp.f2 = make_float2(w, w);
        F2U f0, f1, f2, f3;
        f0.f2 = __half22float2(*(__half2*)&hv.x);
        f1.f2 = __half22float2(*(__half2*)&hv.y);
        f2.f2 = __half22float2(*(__half2*)&hv.z);
        f3.f2 = __half22float2(*(__half2*)&hv.w);
        a0 = ffma2(wp, f0, a0);
        a1 = ffma2(wp, f1, a1);
        a2 = ffma2(wp, f2, a2);
        a3 = ffma2(wp, f3, a3);
    }
    float inv = (sumw > 0.f) ? (1.0f / sumw) : 0.f;
    float* op = g_agg + (size_t)n * DD + q * 8;
    *(float4*)op = make_float4(a0.f2.x * inv, a0.f2.y * inv,
                               a1.f2.x * inv, a1.f2.y * inv);
    *(float4*)(op + 4) = make_float4(a2.f2.x * inv, a2.f2.y * inv,
                                     a3.f2.x * inv, a3.f2.y * inv);
    if (q == 0) g_has[n] = (sumw > 0.f) ? 1.0f : 0.0f;
}

// ---------------- K5: out = agg@Wm + has*bm + x@Wr + br ---------------------
#define SA_STRIDE 260
__global__ void __launch_bounds__(256, 1) k_out(
    const float* __restrict__ x,
    const float* __restrict__ Wm, const float* __restrict__ bm,
    const float* __restrict__ Wr, const float* __restrict__ br,
    float* __restrict__ out) {
    cudaGridDependencySynchronize();  // PDL: wait for k_agg results
    __shared__ float sAk[32 * SA_STRIDE];  // [k within chunk][node]
    __shared__ float sWs[32 * 64];         // [k within chunk][col]

    int t = threadIdx.x;
    int cg = t & 7;
    int ng = t >> 3;
    int nb0 = blockIdx.x * 256;

    float4 bm0 = __ldg((const float4*)(bm + cg * 8));
    float4 bm1 = __ldg((const float4*)(bm + cg * 8 + 4));
    float4 br0 = __ldg((const float4*)(br + cg * 8));
    float4 br1 = __ldg((const float4*)(br + cg * 8 + 4));

    F2U acc[8][4];
#pragma unroll
    for (int i = 0; i < 8; i++)
#pragma unroll
        for (int p = 0; p < 4; p++) acc[i][p].u = 0ull;

    int node = nb0 + t;
    for (int kc = 0; kc < 4; kc++) {
        const float* Asrc = (kc < 2) ? g_agg : x;
        int koff = (kc < 2) ? kc * 32 : (kc - 2) * 32;
        const float* Wsrc = (kc < 2) ? (Wm + kc * 32 * 64) : (Wr + (kc - 2) * 32 * 64);
        __syncthreads();
        const float4* ap = (const float4*)(Asrc + (size_t)node * DD + koff);
#pragma unroll
        for (int kq = 0; kq < 8; kq++) {
            float4 v = (node < NN) ? __ldg(&ap[kq]) : make_float4(0.f, 0.f, 0.f, 0.f);
            sAk[(kq * 4 + 0) * SA_STRIDE + t] = v.x;
            sAk[(kq * 4 + 1) * SA_STRIDE + t] = v.y;
            sAk[(kq * 4 + 2) * SA_STRIDE + t] = v.z;
            sAk[(kq * 4 + 3) * SA_STRIDE + t] = v.w;
        }
        ((float4*)sWs)[t] = __ldg(&((const float4*)Wsrc)[t]);
        ((float4*)sWs)[t + 256] = __ldg(&((const float4*)Wsrc)[t + 256]);
        __syncthreads();

#pragma unroll 4
        for (int kk = 0; kk < 32; kk++) {
            float4 wa = *(const float4*)&sWs[kk * 64 + cg * 8];
            float4 wb = *(const float4*)&sWs[kk * 64 + cg * 8 + 4];
            F2U w0, w1, w2, w3;
            w0.f2 = make_float2(wa.x, wa.y); w1.f2 = make_float2(wa.z, wa.w);
            w2.f2 = make_float2(wb.x, wb.y); w3.f2 = make_float2(wb.z, wb.w);
            float4 a03 = *(const float4*)&sAk[kk * SA_STRIDE + ng * 8];
            float4 a47 = *(const float4*)&sAk[kk * SA_STRIDE + ng * 8 + 4];
            float av[8] = {a03.x, a03.y, a03.z, a03.w, a47.x, a47.y, a47.z, a47.w};
#pragma unroll
            for (int i = 0; i < 8; i++) {
                F2U ap2; ap2.f2 = make_float2(av[i], av[i]);
                acc[i][0] = ffma2(ap2, w0, acc[i][0]);
                acc[i][1] = ffma2(ap2, w1, acc[i][1]);
                acc[i][2] = ffma2(ap2, w2, acc[i][2]);
                acc[i][3] = ffma2(ap2, w3, acc[i][3]);
            }
        }
    }

#pragma unroll
    for (int i = 0; i < 8; i++) {
        int n = nb0 + ng * 8 + i;
        if (n >= NN) break;
        float h = g_has[n];
        float4 o0 = make_float4(acc[i][0].f2.x + h * bm0.x + br0.x,
                                acc[i][0].f2.y + h * bm0.y + br0.y,
                                acc[i][1].f2.x + h * bm0.z + br0.z,
                                acc[i][1].f2.y + h * bm0.w + br0.w);
        float4 o1 = make_float4(acc[i][2].f2.x + h * bm1.x + br1.x,
                                acc[i][2].f2.y + h * bm1.y + br1.y,
                                acc[i][3].f2.x + h * bm1.z + br1.z,
                                acc[i][3].f2.y + h * bm1.w + br1.w);
        float* op = out + (size_t)n * DD + cg * 8;
        *(float4*)op = o0;
        *(float4*)(op + 4) = o1;
    }
}

// ---------------- launcher (PDL-chained dependent launches) ------------------
template <typename F, typename... Args>
static void launch_pdl(F func, dim3 grid, dim3 block, Args... args) {
    cudaLaunchConfig_t cfg = {};
    cfg.gridDim = grid;
    cfg.blockDim = block;
    cudaLaunchAttribute attr[1];
    attr[0].id = cudaLaunchAttributeProgrammaticStreamSerialization;
    attr[0].val.programmaticStreamSerializationAllowed = 1;
    cfg.attrs = attr;
    cfg.numAttrs = 1;
    cudaLaunchKernelEx(&cfg, func, args...);
}

extern "C" void kernel_launch(void* const* d_in, const int* in_sizes, int n_in,
                              void* d_out, int out_size) {
    const float* x  = (const float*)d_in[0];
    const void*  ei = d_in[1];
    const float* Wm = (const float*)d_in[2];
    const float* bm = (const float*)d_in[3];
    const float* Wr = (const float*)d_in[4];
    const float* br = (const float*)d_in[5];
    float* out = (float*)d_out;

    k_fused<<<EDGE_B8 + SN_BLOCKS, 256>>>(x, ei, Wm, bm);
    launch_pdl(k_scan, dim3(SCAN_B), dim3(SCAN_T));
    launch_pdl(k_scatter, dim3(EDGE_B8), dim3(256));
    launch_pdl(k_agg, dim3((NGROUPS * 32 + 255) / 256), dim3(256));
    launch_pdl(k_out, dim3(SN_BLOCKS), dim3(256), x, Wm, bm, Wr, br, out);
}

// round 15
// speedup vs baseline: 1.1318x; 1.0107x over previous
#include <cuda_runtime.h>
#include <cuda_fp16.h>

#define NN 100000
#define EE 1600000
#define DD 64
#define SCAN_T 1024
#define SCAN_B 98                  // ceil(NN/1024)
#define EDGE_B8 782                // ceil(EE/2048): 8 edges/thread blocks
#define SN_BLOCKS 391              // ceil(NN/256)
#define NGROUPS (NN / 4)           // 25000 exact: 4 nodes per warp

// ---------------- scratch (static device globals; zero-init at load) --------
// Invariants at entry: g_deg, g_scanstate, g_smaxkey are ZERO.
// True at load; restored by k_scatter every run (graph replays full sequence).
__device__ unsigned g_smaxkey;
__device__ float    g_snode[NN];             // score, then exp(s-gmax) in-place
__device__ float    g_has[NN];
__device__ int      g_deg[NN];
__device__ int      g_off[NN + 1];
__device__ int      g_cur[NN];
__device__ int2     g_rc[EE];                // interleaved (row, col)
__device__ int2     g_edge[EE];              // CSR-by-dest: (srcRow, bits(w))
__device__ __half2  g_xh[(size_t)NN * 32];   // fp16 mirror of x
__device__ float    g_agg[(size_t)NN * DD];
__device__ unsigned long long g_scanstate[SCAN_B];  // (flag<<32)|value

// ---------------- packed f32x2 FMA (2x fp32 FMA rate on sm_103a) ------------
union F2U { float2 f2; unsigned long long u; };
__device__ __forceinline__ F2U ffma2(F2U a, F2U b, F2U c) {
    F2U d;
    asm("fma.rn.f32x2 %0, %1, %2, %3;" : "=l"(d.u) : "l"(a.u), "l"(b.u), "l"(c.u));
    return d;
}

// ---------------- K1: FUSED (edges, 8/thread) || (scores + fp16 copy) -------
__global__ void __launch_bounds__(256) k_fused(
    const float* __restrict__ x, const void* __restrict__ ei,
    const float* __restrict__ Wm, const float* __restrict__ bm) {
    int b = blockIdx.x;
    int t = threadIdx.x;
    if (b < EDGE_B8) {
        // int64 detection: leading odd 32-bit words all zero <=> int64 ids.
        int2 probe = __ldg(&((const int2*)ei)[t]);
        int any = __syncthreads_or(probe.y);
        int e0 = b * 2048 + t;
        int row[8], col[8];
        if (any == 0) {  // int64
            const long long* p = (const long long*)ei;
#pragma unroll
            for (int k = 0; k < 8; k++) {
                int e = e0 + k * 256;
                if (e < EE) {
                    row[k] = (int)__ldg(&p[e]);
                    col[k] = (int)__ldg(&p[(long long)EE + e]);
                }
            }
        } else {         // int32
            const int* p = (const int*)ei;
#pragma unroll
            for (int k = 0; k < 8; k++) {
                int e = e0 + k * 256;
                if (e < EE) {
                    row[k] = __ldg(&p[e]);
                    col[k] = __ldg(&p[EE + e]);
                }
            }
        }
#pragma unroll
        for (int k = 0; k < 8; k++) {
            int e = e0 + k * 256;
            if (e < EE) {
                g_rc[e] = make_int2(row[k], col[k]);
                atomicAdd(&g_deg[col[k]], 1);
            }
        }
    } else {
        // ---- per-node score s = x[n].wbar + bmean ----
        __shared__ float swb[DD];
        __shared__ float sbm;
        if (t < DD) {
            float s = 0.f;
#pragma unroll
            for (int j = 0; j < DD; j++) s += __ldg(&Wm[t * DD + j]);
            swb[t] = s * (1.0f / DD);
        }
        if (t == 0) {
            float bs = 0.f;
            for (int j = 0; j < DD; j++) bs += __ldg(&bm[j]);
            sbm = bs * (1.0f / DD);
        }
        __syncthreads();
        int n0 = (b - EDGE_B8) * 256;
        int n = n0 + t;
        float s = -1e30f;
        if (n < NN) {
            const float4* xp = (const float4*)(x + (size_t)n * DD);
            float acc = 0.f;
#pragma unroll
            for (int i = 0; i < DD / 4; i++) {
                float4 v = __ldg(&xp[i]);
                acc += v.x * swb[4 * i] + v.y * swb[4 * i + 1] +
                       v.z * swb[4 * i + 2] + v.w * swb[4 * i + 3];
            }
            s = acc + sbm;  // BETA = 1.0
            g_snode[n] = s;
        }
        float m = s;
#pragma unroll
        for (int o = 16; o; o >>= 1) m = fmaxf(m, __shfl_xor_sync(0xffffffffu, m, o));
        if ((t & 31) == 0) {
            unsigned bb = __float_as_uint(m);
            unsigned key = (bb & 0x80000000u) ? ~bb : (bb | 0x80000000u);
            atomicMax(&g_smaxkey, key);
        }
        // ---- fp16 mirror, coalesced ----
        int lim = (NN - n0 < 256) ? (NN - n0) : 256;
        for (int j = t; j < lim * 32; j += 256) {
            int node = n0 + (j >> 5);
            int h = j & 31;
            float2 v = __ldg((const float2*)(x + (size_t)node * DD + 2 * h));
            g_xh[(size_t)node * 32 + h] = __floats2half2_rn(v.x, v.y);
        }
    }
}

// ---------------- K2: decoupled-lookback scan + snode -> exp(s-gmax) --------
__global__ void __launch_bounds__(SCAN_T) k_scan() {
    cudaGridDependencySynchronize();  // PDL: wait for k_fused results
    int b = blockIdx.x, t = threadIdx.x;
    int i = b * SCAN_T + t;
    int v = (i < NN) ? g_deg[i] : 0;

    if (i < NN) {
        unsigned k = g_smaxkey;
        unsigned bb = (k & 0x80000000u) ? (k ^ 0x80000000u) : ~k;
        float smax = __uint_as_float(bb);
        g_snode[i] = __expf(g_snode[i] - smax);
    }

    int lane = t & 31, wid = t >> 5;
    int inc = v;
#pragma unroll
    for (int o = 1; o < 32; o <<= 1) {
        int u = __shfl_up_sync(0xffffffffu, inc, o);
        if (lane >= o) inc += u;
    }
    __shared__ int wtot[32];
    __shared__ int stotal;
    __shared__ int sprefix;
    if (lane == 31) wtot[wid] = inc;
    __syncthreads();
    if (wid == 0) {
        int s = wtot[lane];
        int sinc = s;
#pragma unroll
        for (int o = 1; o < 32; o <<= 1) {
            int u = __shfl_up_sync(0xffffffffu, sinc, o);
            if (lane >= o) sinc += u;
        }
        wtot[lane] = sinc - s;
        if (lane == 31) stotal = sinc;
    }
    __syncthreads();
    int ex = wtot[wid] + inc - v;
    int total = stotal;

    if (t == 0) {
        if (b == 0) {
            atomicExch(&g_scanstate[0], (2ull << 32) | (unsigned)total);
            sprefix = 0;
        } else {
            atomicExch(&g_scanstate[b], (1ull << 32) | (unsigned)total);
            int prefix = 0;
            for (int j = b - 1; j >= 0;) {
                unsigned long long st;
                do { st = atomicAdd(&g_scanstate[j], 0ull); } while ((st >> 32) == 0ull);
                prefix += (int)(unsigned)st;
                if ((st >> 32) == 2ull) break;
                j--;
            }
            atomicExch(&g_scanstate[b], (2ull << 32) | (unsigned)(prefix + total));
            sprefix = prefix;
        }
    }
    __syncthreads();
    int off = sprefix + ex;
    if (i < NN) { g_off[i] = off; g_cur[i] = off; }
    if (b == SCAN_B - 1 && t == 0) g_off[NN] = sprefix + total;  // == EE
    cudaTriggerProgrammaticLaunchCompletion();  // let k_scatter's prologue begin
}

// ---------------- K3: scatter (srcRow, w) into CSR-by-dest + cleanup --------
__global__ void __launch_bounds__(256) k_scatter() {
    cudaGridDependencySynchronize();  // PDL: wait for k_scan results
    int e0 = blockIdx.x * 2048 + threadIdx.x;
#pragma unroll
    for (int k = 0; k < 8; k++) {
        int e = e0 + k * 256;
        if (e < EE) {
            int2 rc = __ldg(&g_rc[e]);
            float w = __ldg(&g_snode[rc.x]);
            int pos = atomicAdd(&g_cur[rc.y], 1);
            g_edge[pos] = make_int2(rc.x, __float_as_int(w));
        }
    }
    // restore zero-invariants for the next graph replay
    int gtid = blockIdx.x * 256 + threadIdx.x;
    for (int i = gtid; i < NN; i += EDGE_B8 * 256) g_deg[i] = 0;
    if (gtid < SCAN_B) g_scanstate[gtid] = 0ull;
    if (gtid == 0) g_smaxkey = 0u;
}

// ---------------- K4: aggregation — 8 lanes/node, 4 nodes/warp, no shuffles -
// Lane owns dims 8q..8q+7 (one fp16 LDG.128 per edge). Edge record carries
// (row, w). unroll 2: best measured balance of MLP vs registers/occupancy.
__global__ void __launch_bounds__(256) k_agg() {
    cudaGridDependencySynchronize();  // PDL: wait for k_scatter results
    int wi = (blockIdx.x * blockDim.x + threadIdx.x) >> 5;  // warp id
    int lane = threadIdx.x & 31;
    if (wi >= NGROUPS) return;
    int g = lane >> 3;   // node slot within warp
    int q = lane & 7;    // dim octet
    int n = wi * 4 + g;
    int beg = g_off[n], end = g_off[n + 1];

    F2U a0, a1, a2, a3;
    a0.u = a1.u = a2.u = a3.u = 0ull;
    float sumw = 0.f;
#pragma unroll 2
    for (int i = beg; i < end; i++) {
        int2 ed = __ldg(&g_edge[i]);
        float w = __int_as_float(ed.y);
        sumw += w;
        uint4 hv = __ldg((const uint4*)(g_xh + (size_t)ed.x * 32 + q * 4));
        F2U wp; wp.f2 = make_float2(w, w);
        F2U f0, f1, f2, f3;
        f0.f2 = __half22float2(*(__half2*)&hv.x);
        f1.f2 = __half22float2(*(__half2*)&hv.y);
        f2.f2 = __half22float2(*(__half2*)&hv.z);
        f3.f2 = __half22float2(*(__half2*)&hv.w);
        a0 = ffma2(wp, f0, a0);
        a1 = ffma2(wp, f1, a1);
        a2 = ffma2(wp, f2, a2);
        a3 = ffma2(wp, f3, a3);
    }
    float inv = (sumw > 0.f) ? (1.0f / sumw) : 0.f;
    float* op = g_agg + (size_t)n * DD + q * 8;
    *(float4*)op = make_float4(a0.f2.x * inv, a0.f2.y * inv,
                               a1.f2.x * inv, a1.f2.y * inv);
    *(float4*)(op + 4) = make_float4(a2.f2.x * inv, a2.f2.y * inv,
                                     a3.f2.x * inv, a3.f2.y * inv);
    if (q == 0) g_has[n] = (sumw > 0.f) ? 1.0f : 0.0f;
}

// ---------------- K5: out = agg@Wm + has*bm + x@Wr + br ---------------------
#define SA_STRIDE 260
__global__ void __launch_bounds__(256, 1) k_out(
    const float* __restrict__ x,
    const float* __restrict__ Wm, const float* __restrict__ bm,
    const float* __restrict__ Wr, const float* __restrict__ br,
    float* __restrict__ out) {
    cudaGridDependencySynchronize();  // PDL: wait for k_agg results
    __shared__ float sAk[32 * SA_STRIDE];  // [k within chunk][node]
    __shared__ float sWs[32 * 64];         // [k within chunk][col]

    int t = threadIdx.x;
    int cg = t & 7;
    int ng = t >> 3;
    int nb0 = blockIdx.x * 256;

    float4 bm0 = __ldg((const float4*)(bm + cg * 8));
    float4 bm1 = __ldg((const float4*)(bm + cg * 8 + 4));
    float4 br0 = __ldg((const float4*)(br + cg * 8));
    float4 br1 = __ldg((const float4*)(br + cg * 8 + 4));

    F2U acc[8][4];
#pragma unroll
    for (int i = 0; i < 8; i++)
#pragma unroll
        for (int p = 0; p < 4; p++) acc[i][p].u = 0ull;

    int node = nb0 + t;
    for (int kc = 0; kc < 4; kc++) {
        const float* Asrc = (kc < 2) ? g_agg : x;
        int koff = (kc < 2) ? kc * 32 : (kc - 2) * 32;
        const float* Wsrc = (kc < 2) ? (Wm + kc * 32 * 64) : (Wr + (kc - 2) * 32 * 64);
        __syncthreads();
        const float4* ap = (const float4*)(Asrc + (size_t)node * DD + koff);
#pragma unroll
        for (int kq = 0; kq < 8; kq++) {
            float4 v = (node < NN) ? __ldg(&ap[kq]) : make_float4(0.f, 0.f, 0.f, 0.f);
            sAk[(kq * 4 + 0) * SA_STRIDE + t] = v.x;
            sAk[(kq * 4 + 1) * SA_STRIDE + t] = v.y;
            sAk[(kq * 4 + 2) * SA_STRIDE + t] = v.z;
            sAk[(kq * 4 + 3) * SA_STRIDE + t] = v.w;
        }
        ((float4*)sWs)[t] = __ldg(&((const float4*)Wsrc)[t]);
        ((float4*)sWs)[t + 256] = __ldg(&((const float4*)Wsrc)[t + 256]);
        __syncthreads();

#pragma unroll 4
        for (int kk = 0; kk < 32; kk++) {
            float4 wa = *(const float4*)&sWs[kk * 64 + cg * 8];
            float4 wb = *(const float4*)&sWs[kk * 64 + cg * 8 + 4];
            F2U w0, w1, w2, w3;
            w0.f2 = make_float2(wa.x, wa.y); w1.f2 = make_float2(wa.z, wa.w);
            w2.f2 = make_float2(wb.x, wb.y); w3.f2 = make_float2(wb.z, wb.w);
            float4 a03 = *(const float4*)&sAk[kk * SA_STRIDE + ng * 8];
            float4 a47 = *(const float4*)&sAk[kk * SA_STRIDE + ng * 8 + 4];
            float av[8] = {a03.x, a03.y, a03.z, a03.w, a47.x, a47.y, a47.z, a47.w};
#pragma unroll
            for (int i = 0; i < 8; i++) {
                F2U ap2; ap2.f2 = make_float2(av[i], av[i]);
                acc[i][0] = ffma2(ap2, w0, acc[i][0]);
                acc[i][1] = ffma2(ap2, w1, acc[i][1]);
                acc[i][2] = ffma2(ap2, w2, acc[i][2]);
                acc[i][3] = ffma2(ap2, w3, acc[i][3]);
            }
        }
    }

#pragma unroll
    for (int i = 0; i < 8; i++) {
        int n = nb0 + ng * 8 + i;
        if (n >= NN) break;
        float h = g_has[n];
        float4 o0 = make_float4(acc[i][0].f2.x + h * bm0.x + br0.x,
                                acc[i][0].f2.y + h * bm0.y + br0.y,
                                acc[i][1].f2.x + h * bm0.z + br0.z,
                                acc[i][1].f2.y + h * bm0.w + br0.w);
        float4 o1 = make_float4(acc[i][2].f2.x + h * bm1.x + br1.x,
                                acc[i][2].f2.y + h * bm1.y + br1.y,
                                acc[i][3].f2.x + h * bm1.z + br1.z,
                                acc[i][3].f2.y + h * bm1.w + br1.w);
        float* op = out + (size_t)n * DD + cg * 8;
        *(float4*)op = o0;
        *(float4*)(op + 4) = o1;
    }
}

// ---------------- launcher (PDL-chained dependent launches) ------------------
template <typename F, typename... Args>
static void launch_pdl(F func, dim3 grid, dim3 block, Args... args) {
    cudaLaunchConfig_t cfg = {};
    cfg.gridDim = grid;
    cfg.blockDim = block;
    cudaLaunchAttribute attr[1];
    attr[0].id = cudaLaunchAttributeProgrammaticStreamSerialization;
    attr[0].val.programmaticStreamSerializationAllowed = 1;
    cfg.attrs = attr;
    cfg.numAttrs = 1;
    cudaLaunchKernelEx(&cfg, func, args...);
}

extern "C" void kernel_launch(void* const* d_in, const int* in_sizes, int n_in,
                              void* d_out, int out_size) {
    const float* x  = (const float*)d_in[0];
    const void*  ei = d_in[1];
    const float* Wm = (const float*)d_in[2];
    const float* bm = (const float*)d_in[3];
    const float* Wr = (const float*)d_in[4];
    const float* br = (const float*)d_in[5];
    float* out = (float*)d_out;

    k_fused<<<EDGE_B8 + SN_BLOCKS, 256>>>(x, ei, Wm, bm);
    launch_pdl(k_scan, dim3(SCAN_B), dim3(SCAN_T));
    launch_pdl(k_scatter, dim3(EDGE_B8), dim3(256));
    launch_pdl(k_agg, dim3((NGROUPS * 32 + 255) / 256), dim3(256));
    launch_pdl(k_out, dim3(SN_BLOCKS), dim3(256), x, Wm, bm, Wr, br, out);
}